// round 11
// baseline (speedup 1.0000x reference)
#include <cuda_runtime.h>
#include <math.h>
#include <stdint.h>

#define NSEQ 10000
#define LSEQ 32
#define DIM  256
#define GDIM 1024
#define KDIM 512
#define GRID 296         // 2 CTAs per SM (148 SMs), one wave
#define NTHR 256
#define RP   48          // padded rows per CTA (3 x m16 tiles), actual rows 33-34
#define MT   3           // m16 tiles per CTA
#define PSTRIDE 516      // stride mod 32 banks = 4 -> lane bank = g*4+tig, conflict-free
#define FR4  (4 * MT * 8 * 32)        // float4 state frags per CTA = 3072
#define FRF  (FR4 * 4)                // floats per CTA state = 12288

// ---------------- device scratch (no runtime allocation allowed) ----------------
__device__ float g_Wfrag[524288];        // fused [W_ih;W_hh] in exact B-fragment order, tf32-rounded
__device__ float g_bias[GDIM];           // b_ih + b_hh, original (gate,j) order
__device__ float g_hfrag[GRID * FRF];    // per-CTA h state, fragment order (float4/thread)
__device__ float g_cfrag[GRID * FRF];    // per-CTA c state, fragment order

// ---------------- helpers ----------------
__device__ __forceinline__ float sigf(float x) {
    return __fdividef(1.0f, 1.0f + __expf(-x));
}
__device__ __forceinline__ float tanhf_(float x) {
    return fmaf(2.0f, __fdividef(1.0f, 1.0f + __expf(-2.0f * x)), -1.0f);
}
__device__ __forceinline__ float tf32r(float x) {
    uint32_t u; asm("cvt.rna.tf32.f32 %0, %1;" : "=r"(u) : "f"(x));
    return __uint_as_float(u);
}
__device__ __forceinline__ void mma_tf32(float c[4],
                                         uint32_t a0, uint32_t a1, uint32_t a2, uint32_t a3,
                                         uint32_t b0, uint32_t b1) {
    asm volatile(
        "mma.sync.aligned.m16n8k8.row.col.f32.tf32.tf32.f32 "
        "{%0,%1,%2,%3},{%4,%5,%6,%7},{%8,%9},{%0,%1,%2,%3};"
        : "+f"(c[0]), "+f"(c[1]), "+f"(c[2]), "+f"(c[3])
        : "r"(a0), "r"(a1), "r"(a2), "r"(a3), "r"(b0), "r"(b1));
}

// ---------------- prep: build fragment-ordered fused weights + folded bias ----------------
// Gate-column permutation (position p in [0,1024)):
//   nt=p>>8, p8=p&255, w=p8>>5, c32=p8&31, s=c32>>3, c8=c32&7
//   unit u = (s>>1)*4 + (c8>>1); gate = (s&1)*2 + (c8&1)   (0=i,1=f,2=g,3=o)
//   hidden j = nt*64 + w*8 + u;  original W row = gate*256 + j
// B-fragment storage: g_Wfrag[((s8*64+ks)*32+lane)*2 + r] = Wfused[n=s8*8+(lane>>2)][k=ks*8+(lane&3)+4r]
__global__ void prep_kernel(const float* __restrict__ W_ih, const float* __restrict__ W_hh,
                            const float* __restrict__ b_ih, const float* __restrict__ b_hh) {
    int idx0 = blockIdx.x * blockDim.x + threadIdx.x;
    for (int idx = idx0; idx < 524288; idx += gridDim.x * blockDim.x) {
        int r    = idx & 1;
        int lane = (idx >> 1) & 31;
        int ks   = (idx >> 6) & 63;
        int s8   = idx >> 12;
        int n    = s8 * 8 + (lane >> 2);
        int k    = ks * 8 + (lane & 3) + 4 * r;
        int nt = n >> 8, p8 = n & 255;
        int w = p8 >> 5, c32 = p8 & 31, s = c32 >> 3, c8 = c32 & 7;
        int u    = ((s >> 1) << 2) + (c8 >> 1);
        int gate = ((s & 1) << 1) + (c8 & 1);
        int j    = nt * 64 + w * 8 + u;
        int row  = gate * 256 + j;
        float v  = (k < 256) ? W_ih[row * 256 + k] : W_hh[row * 256 + (k - 256)];
        g_Wfrag[idx] = tf32r(v);
    }
    if (idx0 < GDIM) g_bias[idx0] = b_ih[idx0] + b_hh[idx0];
}

// ---------------- fused persistent LSTM (tf32 tensor cores, 2 CTAs/SM) ----------------
__global__ __launch_bounds__(NTHR, 2)
void lstm_fused_kernel(const float* __restrict__ x, const int* __restrict__ lengths,
                       float* __restrict__ out) {
    extern __shared__ float panel[];   // [RP][PSTRIDE]: cols 0..255 = x_t, 256..511 = h_t
    __shared__ float sbias[GDIM];
    __shared__ int   slen[RP];

    const int bid = blockIdx.x;
    const int n0  = (bid * NSEQ) / GRID;
    const int n1  = ((bid + 1) * NSEQ) / GRID;
    const int R   = n1 - n0;           // 33 or 34
    const int tid = threadIdx.x;
    const int w   = tid >> 5, lane = tid & 31, g = lane >> 2, tig = lane & 3;

    float*  hfr  = g_hfrag + (size_t)bid * FRF;
    float*  cfr  = g_cfrag + (size_t)bid * FRF;
    float4* hfr4 = (float4*)hfr;
    float4* cfr4 = (float4*)cfr;

    for (int i = tid; i < GDIM; i += NTHR) sbias[i] = g_bias[i];
    for (int i = tid; i < RP; i += NTHR)   slen[i] = (i < R) ? lengths[n0 + i] : 0;
    for (int i = tid; i < RP * PSTRIDE; i += NTHR) panel[i] = 0.0f;
    for (int i = tid; i < FRF; i += NTHR) { hfr[i] = 0.0f; cfr[i] = 0.0f; }
    __syncthreads();

    for (int t = 0; t < LSEQ; t++) {
        // ---- stage x_t (rows < R; pad rows stay zero) ----
        const float4* xg = (const float4*)(x + (size_t)n0 * LSEQ * DIM + (size_t)t * DIM);
        for (int i = tid; i < R * 64; i += NTHR) {
            int r = i >> 6, c = i & 63;
            float4 v = xg[(size_t)r * 2048 + c];   // row stride = LSEQ*DIM/4
            *(float4*)&panel[r * PSTRIDE + c * 4] = v;
        }
        // ---- stage h_t from fragment-ordered scratch ----
        for (int f = tid; f < FR4; f += NTHR) {
            float4 hv = hfr4[f];
            int nt = f / (MT * 256), rem = f - nt * (MT * 256);
            int m = rem >> 8, rem2 = rem & 255;
            int w2 = rem2 >> 5, lane2 = rem2 & 31;
            int g2 = lane2 >> 2, tg2 = lane2 & 3;
            int j0 = nt * 64 + w2 * 8 + tg2;
            int r0 = m * 16 + g2;
            panel[r0 * PSTRIDE + 256 + j0]           = hv.x;
            panel[(r0 + 8) * PSTRIDE + 256 + j0]     = hv.y;
            panel[r0 * PSTRIDE + 256 + j0 + 4]       = hv.z;
            panel[(r0 + 8) * PSTRIDE + 256 + j0 + 4] = hv.w;
        }
        __syncthreads();

        for (int nt = 0; nt < 4; nt++) {
            const int j = nt * 64 + w * 8 + tig;
            const float bi0 = sbias[j],       bf0 = sbias[256 + j];
            const float bg0 = sbias[512 + j], bo0 = sbias[768 + j];
            const float bi1 = sbias[j + 4],       bf1 = sbias[256 + j + 4];
            const float bg1 = sbias[512 + j + 4], bo1 = sbias[768 + j + 4];

            float C[MT][4][4];
#pragma unroll
            for (int m = 0; m < MT; m++)
#pragma unroll
                for (int s = 0; s < 4; s++)
#pragma unroll
                    for (int q = 0; q < 4; q++) C[m][s][q] = 0.0f;

            const float2* bp[4];
#pragma unroll
            for (int s = 0; s < 4; s++) {
                int s8 = nt * 32 + w * 4 + s;
                bp[s] = (const float2*)g_Wfrag + (size_t)s8 * 2048 + lane;
            }
            float2 Bc[4];
#pragma unroll
            for (int s = 0; s < 4; s++) Bc[s] = bp[s][0];

            int rowb[MT];
#pragma unroll
            for (int m = 0; m < MT; m++) rowb[m] = (m * 16 + g) * PSTRIDE;

#pragma unroll 2
            for (int ks = 0; ks < 64; ks++) {
                float2 Bn[4];
                int ks2 = (ks < 63) ? ks + 1 : 63;
#pragma unroll
                for (int s = 0; s < 4; s++) Bn[s] = bp[s][ks2 * 32];
                const int k = ks * 8 + tig;
#pragma unroll
                for (int m = 0; m < MT; m++) {
                    const float* ap = panel + rowb[m] + k;
                    uint32_t a0 = __float_as_uint(ap[0]);
                    uint32_t a2 = __float_as_uint(ap[4]);
                    uint32_t a1 = __float_as_uint(ap[8 * PSTRIDE]);
                    uint32_t a3 = __float_as_uint(ap[8 * PSTRIDE + 4]);
#pragma unroll
                    for (int s = 0; s < 4; s++)
                        mma_tf32(C[m][s], a0, a1, a2, a3,
                                 __float_as_uint(Bc[s].x), __float_as_uint(Bc[s].y));
                }
#pragma unroll
                for (int s = 0; s < 4; s++) Bc[s] = Bn[s];
            }

            // ---- register-local epilogue: thread holds i,f,g,o of its units ----
#pragma unroll
            for (int m = 0; m < MT; m++) {
                int f4 = ((nt * MT + m) * 8 + w) * 32 + lane;
                float4 cold = cfr4[f4];
                float4 hold = hfr4[f4];
                int r0 = m * 16 + g, r1 = r0 + 8;
                bool v0 = t < slen[r0], v1 = t < slen[r1];
                float4 cn, hn;
                {   // q0: unit tig, row r0
                    float ii = sigf(C[m][0][0] + bi0), ff = sigf(C[m][0][1] + bf0);
                    float gg = tanhf_(C[m][1][0] + bg0), oo = sigf(C[m][1][1] + bo0);
                    float c2 = fmaf(ff, cold.x, ii * gg);
                    float h2 = oo * tanhf_(c2);
                    cn.x = v0 ? c2 : cold.x;  hn.x = v0 ? h2 : hold.x;
                }
                {   // q1: unit tig, row r1
                    float ii = sigf(C[m][0][2] + bi0), ff = sigf(C[m][0][3] + bf0);
                    float gg = tanhf_(C[m][1][2] + bg0), oo = sigf(C[m][1][3] + bo0);
                    float c2 = fmaf(ff, cold.y, ii * gg);
                    float h2 = oo * tanhf_(c2);
                    cn.y = v1 ? c2 : cold.y;  hn.y = v1 ? h2 : hold.y;
                }
                {   // q2: unit tig+4, row r0
                    float ii = sigf(C[m][2][0] + bi1), ff = sigf(C[m][2][1] + bf1);
                    float gg = tanhf_(C[m][3][0] + bg1), oo = sigf(C[m][3][1] + bo1);
                    float c2 = fmaf(ff, cold.z, ii * gg);
                    float h2 = oo * tanhf_(c2);
                    cn.z = v0 ? c2 : cold.z;  hn.z = v0 ? h2 : hold.z;
                }
                {   // q3: unit tig+4, row r1
                    float ii = sigf(C[m][2][2] + bi1), ff = sigf(C[m][2][3] + bf1);
                    float gg = tanhf_(C[m][3][2] + bg1), oo = sigf(C[m][3][3] + bo1);
                    float c2 = fmaf(ff, cold.w, ii * gg);
                    float h2 = oo * tanhf_(c2);
                    cn.w = v1 ? c2 : cold.w;  hn.w = v1 ? h2 : hold.w;
                }
                cfr4[f4] = cn;
                hfr4[f4] = hn;
            }
        }
        __syncthreads();   // all mma reads + epilogue writes done before restaging
    }

    // ---- write final h (un-permute fragment order) ----
    for (int f = tid; f < FR4; f += NTHR) {
        float4 hv = hfr4[f];
        int nt = f / (MT * 256), rem = f - nt * (MT * 256);
        int m = rem >> 8, rem2 = rem & 255;
        int w2 = rem2 >> 5, lane2 = rem2 & 31;
        int g2 = lane2 >> 2, tg2 = lane2 & 3;
        int j0 = nt * 64 + w2 * 8 + tg2;
        int r0 = m * 16 + g2, r1 = r0 + 8;
        if (r0 < R) {
            out[(size_t)(n0 + r0) * DIM + j0]     = hv.x;
            out[(size_t)(n0 + r0) * DIM + j0 + 4] = hv.z;
        }
        if (r1 < R) {
            out[(size_t)(n0 + r1) * DIM + j0]     = hv.y;
            out[(size_t)(n0 + r1) * DIM + j0 + 4] = hv.w;
        }
    }
}

// ---------------- launch ----------------
extern "C" void kernel_launch(void* const* d_in, const int* in_sizes, int n_in,
                              void* d_out, int out_size) {
    const float* x       = (const float*)d_in[0];
    const int*   lengths = (const int*)d_in[1];
    const float* W_ih    = (const float*)d_in[2];
    const float* W_hh    = (const float*)d_in[3];
    const float* b_ih    = (const float*)d_in[4];
    const float* b_hh    = (const float*)d_in[5];
    float*       out     = (float*)d_out;
    (void)in_sizes; (void)n_in; (void)out_size;

    prep_kernel<<<512, 256>>>(W_ih, W_hh, b_ih, b_hh);

    const int smem = RP * PSTRIDE * 4;   // 99072 B -> 2 CTAs/SM fit in 228KB
    (void)cudaFuncSetAttribute(lstm_fused_kernel,
                               cudaFuncAttributeMaxDynamicSharedMemorySize, smem);
    lstm_fused_kernel<<<GRID, NTHR, smem>>>(x, lengths, out);
}

// round 12
// speedup vs baseline: 2.2002x; 2.2002x over previous
#include <cuda_runtime.h>
#include <cuda_fp16.h>
#include <math.h>
#include <stdint.h>

#define NSEQ 10000
#define LSEQ 32
#define DIM  256
#define GDIM 1024
#define GRID 148
#define NTHR 256
#define RP   80          // padded rows per CTA (5 x m16 tiles)
#define PSH  520         // panel row stride in HALVES; 520/2=260 words, mod 32 = 4 -> conflict-free

// ---------------- device scratch (no runtime allocation allowed) ----------------
__device__ __half g_Whalf[524288];       // fused [W_ih;W_hh] in fp16 B-fragment order
__device__ float  g_bias[GDIM];          // b_ih + b_hh
__device__ float  g_hfrag[GRID * 20480]; // per-CTA h state fp32, fragment order
__device__ float  g_cfrag[GRID * 20480]; // per-CTA c state fp32, fragment order

// ---------------- helpers ----------------
__device__ __forceinline__ float sigf(float x) {
    return __fdividef(1.0f, 1.0f + __expf(-x));
}
__device__ __forceinline__ float tanhf_(float x) {
    return fmaf(2.0f, __fdividef(1.0f, 1.0f + __expf(-2.0f * x)), -1.0f);
}
__device__ __forceinline__ void mma_f16(float c[4],
                                        uint32_t a0, uint32_t a1, uint32_t a2, uint32_t a3,
                                        uint32_t b0, uint32_t b1) {
    asm volatile(
        "mma.sync.aligned.m16n8k16.row.col.f32.f16.f16.f32 "
        "{%0,%1,%2,%3},{%4,%5,%6,%7},{%8,%9},{%0,%1,%2,%3};"
        : "+f"(c[0]), "+f"(c[1]), "+f"(c[2]), "+f"(c[3])
        : "r"(a0), "r"(a1), "r"(a2), "r"(a3), "r"(b0), "r"(b1));
}

// ---------------- prep: fp16 B-fragment weights + folded bias ----------------
// Global column position p (0..1023) -> logical (gate, j) permutation (as before):
//   nt=p>>8, p8=p&255, w=p8>>5, c32=p8&31, s=c32>>3, c8=c32&7
//   u=(s>>1)*4+(c8>>1); gate=(s&1)*2+(c8&1); j=nt*64+w*8+u; W row = gate*256+j
// fp16 m16n8k16 B fragment: uint2 per (s8, ks, lane):
//   .x halves = W[n][k=ks*16+2*tig + {0,1}], .y halves = W[n][k=ks*16+2*tig+8 + {0,1}], n=s8*8+g
__global__ void prep_kernel(const float* __restrict__ W_ih, const float* __restrict__ W_hh,
                            const float* __restrict__ b_ih, const float* __restrict__ b_hh) {
    int idx0 = blockIdx.x * blockDim.x + threadIdx.x;
    for (int idx = idx0; idx < 524288; idx += gridDim.x * blockDim.x) {
        int q    = idx & 3;            // 0,1 -> b0 halves; 2,3 -> b1 halves
        int lane = (idx >> 2) & 31;
        int ks   = (idx >> 7) & 31;
        int s8   = idx >> 12;
        int g    = lane >> 2, tig = lane & 3;
        int r    = q >> 1, hh = q & 1;
        int k    = ks * 16 + tig * 2 + r * 8 + hh;
        int p    = s8 * 8 + g;
        int nt = p >> 8, p8 = p & 255;
        int w = p8 >> 5, c32 = p8 & 31, s = c32 >> 3, c8 = c32 & 7;
        int u    = ((s >> 1) << 2) + (c8 >> 1);
        int gate = ((s & 1) << 1) + (c8 & 1);
        int j    = nt * 64 + w * 8 + u;
        int row  = gate * 256 + j;
        float v  = (k < 256) ? W_ih[row * 256 + k] : W_hh[row * 256 + (k - 256)];
        g_Whalf[idx] = __float2half(v);
    }
    if (idx0 < GDIM) g_bias[idx0] = b_ih[idx0] + b_hh[idx0];
}

// ---------------- fused persistent LSTM (fp16 tensor cores, fp32 accum/state) ----------------
__global__ __launch_bounds__(NTHR, 1)
void lstm_fused_kernel(const float* __restrict__ x, const int* __restrict__ lengths,
                       float* __restrict__ out) {
    extern __shared__ __half panel[];   // [RP][PSH]: cols 0..255 = x_t, 256..511 = h_t (fp16)
    __shared__ float sbias[GDIM];
    __shared__ int   slen[RP];

    const int bid = blockIdx.x;
    const int n0  = (bid * NSEQ) / GRID;
    const int n1  = ((bid + 1) * NSEQ) / GRID;
    const int R   = n1 - n0;           // 67 or 68
    const int tid = threadIdx.x;
    const int w   = tid >> 5, lane = tid & 31, g = lane >> 2, tig = lane & 3;

    float*  hfr  = g_hfrag + (size_t)bid * 20480;
    float*  cfr  = g_cfrag + (size_t)bid * 20480;
    float4* hfr4 = (float4*)hfr;
    float4* cfr4 = (float4*)cfr;

    for (int i = tid; i < GDIM; i += NTHR) sbias[i] = g_bias[i];
    for (int i = tid; i < RP; i += NTHR)   slen[i] = (i < R) ? lengths[n0 + i] : 0;
    for (int i = tid; i < RP * PSH / 2; i += NTHR) ((uint32_t*)panel)[i] = 0u;
    for (int i = tid; i < 20480; i += NTHR) { hfr[i] = 0.0f; cfr[i] = 0.0f; }
    __syncthreads();

    const uint2* gW2 = (const uint2*)&g_Whalf[0];

    for (int t = 0; t < LSEQ; t++) {
        // ---- stage x_t as fp16 (rows < R; pad rows stay zero) ----
        const float4* xg = (const float4*)(x + (size_t)n0 * LSEQ * DIM + (size_t)t * DIM);
        for (int i = tid; i < R * 64; i += NTHR) {
            int r = i >> 6, c = i & 63;
            float4 v = xg[(size_t)r * 2048 + c];   // row stride = LSEQ*DIM/4
            __half2 h01 = __floats2half2_rn(v.x, v.y);
            __half2 h23 = __floats2half2_rn(v.z, v.w);
            *(__half2*)&panel[r * PSH + c * 4]     = h01;
            *(__half2*)&panel[r * PSH + c * 4 + 2] = h23;
        }
        // ---- stage h_t (fp32 fragment scratch -> fp16 panel scatter) ----
        for (int f = tid; f < 5120; f += NTHR) {
            float4 hv = hfr4[f];
            int nt = f / 1280, rem = f - nt * 1280;
            int m = rem >> 8, rem2 = rem & 255;
            int w2 = rem2 >> 5, lane2 = rem2 & 31;
            int g2 = lane2 >> 2, tg2 = lane2 & 3;
            int j0 = nt * 64 + w2 * 8 + tg2;
            int r0 = m * 16 + g2;
            panel[r0 * PSH + 256 + j0]           = __float2half(hv.x);
            panel[(r0 + 8) * PSH + 256 + j0]     = __float2half(hv.y);
            panel[r0 * PSH + 256 + j0 + 4]       = __float2half(hv.z);
            panel[(r0 + 8) * PSH + 256 + j0 + 4] = __float2half(hv.w);
        }
        __syncthreads();

        for (int nt = 0; nt < 4; nt++) {
            const int j = nt * 64 + w * 8 + tig;
            const float bi0 = sbias[j],       bf0 = sbias[256 + j];
            const float bg0 = sbias[512 + j], bo0 = sbias[768 + j];
            const float bi1 = sbias[j + 4],       bf1 = sbias[256 + j + 4];
            const float bg1 = sbias[512 + j + 4], bo1 = sbias[768 + j + 4];

            float C[5][4][4];
#pragma unroll
            for (int m = 0; m < 5; m++)
#pragma unroll
                for (int s = 0; s < 4; s++)
#pragma unroll
                    for (int q = 0; q < 4; q++) C[m][s][q] = 0.0f;

            const uint2* bp[4];
#pragma unroll
            for (int s = 0; s < 4; s++) {
                int s8 = nt * 32 + w * 4 + s;
                bp[s] = gW2 + (size_t)s8 * 1024 + lane;
            }
            uint2 Bc[4];
#pragma unroll
            for (int s = 0; s < 4; s++) Bc[s] = bp[s][0];

            int rowb[5];
#pragma unroll
            for (int m = 0; m < 5; m++) rowb[m] = (m * 16 + g) * PSH;

#pragma unroll 2
            for (int ks = 0; ks < 32; ks++) {
                uint2 Bn[4];
                int ks2 = (ks < 31) ? ks + 1 : 31;
#pragma unroll
                for (int s = 0; s < 4; s++) Bn[s] = bp[s][ks2 * 32];
                const int k0 = ks * 16 + tig * 2;
#pragma unroll
                for (int m = 0; m < 5; m++) {
                    const __half* ap = panel + rowb[m] + k0;
                    uint32_t a0 = *(const uint32_t*)ap;
                    uint32_t a2 = *(const uint32_t*)(ap + 8);
                    uint32_t a1 = *(const uint32_t*)(ap + 8 * PSH);
                    uint32_t a3 = *(const uint32_t*)(ap + 8 * PSH + 8);
#pragma unroll
                    for (int s = 0; s < 4; s++)
                        mma_f16(C[m][s], a0, a1, a2, a3, Bc[s].x, Bc[s].y);
                }
#pragma unroll
                for (int s = 0; s < 4; s++) Bc[s] = Bn[s];
            }

            // ---- register-local epilogue: thread holds i,f,g,o of its units (fp32) ----
#pragma unroll
            for (int m = 0; m < 5; m++) {
                int f4 = ((nt * 5 + m) * 8 + w) * 32 + lane;
                float4 cold = cfr4[f4];
                float4 hold = hfr4[f4];
                int r0 = m * 16 + g, r1 = r0 + 8;
                bool v0 = t < slen[r0], v1 = t < slen[r1];
                float4 cn, hn;
                {   // q0: unit tig, row r0
                    float ii = sigf(C[m][0][0] + bi0), ff = sigf(C[m][0][1] + bf0);
                    float gg = tanhf_(C[m][1][0] + bg0), oo = sigf(C[m][1][1] + bo0);
                    float c2 = fmaf(ff, cold.x, ii * gg);
                    float h2 = oo * tanhf_(c2);
                    cn.x = v0 ? c2 : cold.x;  hn.x = v0 ? h2 : hold.x;
                }
                {   // q1: unit tig, row r1
                    float ii = sigf(C[m][0][2] + bi0), ff = sigf(C[m][0][3] + bf0);
                    float gg = tanhf_(C[m][1][2] + bg0), oo = sigf(C[m][1][3] + bo0);
                    float c2 = fmaf(ff, cold.y, ii * gg);
                    float h2 = oo * tanhf_(c2);
                    cn.y = v1 ? c2 : cold.y;  hn.y = v1 ? h2 : hold.y;
                }
                {   // q2: unit tig+4, row r0
                    float ii = sigf(C[m][2][0] + bi1), ff = sigf(C[m][2][1] + bf1);
                    float gg = tanhf_(C[m][3][0] + bg1), oo = sigf(C[m][3][1] + bo1);
                    float c2 = fmaf(ff, cold.z, ii * gg);
                    float h2 = oo * tanhf_(c2);
                    cn.z = v0 ? c2 : cold.z;  hn.z = v0 ? h2 : hold.z;
                }
                {   // q3: unit tig+4, row r1
                    float ii = sigf(C[m][2][2] + bi1), ff = sigf(C[m][2][3] + bf1);
                    float gg = tanhf_(C[m][3][2] + bg1), oo = sigf(C[m][3][3] + bo1);
                    float c2 = fmaf(ff, cold.w, ii * gg);
                    float h2 = oo * tanhf_(c2);
                    cn.w = v1 ? c2 : cold.w;  hn.w = v1 ? h2 : hold.w;
                }
                cfr4[f4] = cn;
                hfr4[f4] = hn;
            }
        }
        __syncthreads();   // all mma reads + epilogue writes done before restaging
    }

    // ---- write final h (un-permute fragment order, fp32 exact) ----
    for (int f = tid; f < 5120; f += NTHR) {
        float4 hv = hfr4[f];
        int nt = f / 1280, rem = f - nt * 1280;
        int m = rem >> 8, rem2 = rem & 255;
        int w2 = rem2 >> 5, lane2 = rem2 & 31;
        int g2 = lane2 >> 2, tg2 = lane2 & 3;
        int j0 = nt * 64 + w2 * 8 + tg2;
        int r0 = m * 16 + g2, r1 = r0 + 8;
        if (r0 < R) {
            out[(size_t)(n0 + r0) * DIM + j0]     = hv.x;
            out[(size_t)(n0 + r0) * DIM + j0 + 4] = hv.z;
        }
        if (r1 < R) {
            out[(size_t)(n0 + r1) * DIM + j0]     = hv.y;
            out[(size_t)(n0 + r1) * DIM + j0 + 4] = hv.w;
        }
    }
}

// ---------------- launch ----------------
extern "C" void kernel_launch(void* const* d_in, const int* in_sizes, int n_in,
                              void* d_out, int out_size) {
    const float* x       = (const float*)d_in[0];
    const int*   lengths = (const int*)d_in[1];
    const float* W_ih    = (const float*)d_in[2];
    const float* W_hh    = (const float*)d_in[3];
    const float* b_ih    = (const float*)d_in[4];
    const float* b_hh    = (const float*)d_in[5];
    float*       out     = (float*)d_out;
    (void)in_sizes; (void)n_in; (void)out_size;

    prep_kernel<<<512, 256>>>(W_ih, W_hh, b_ih, b_hh);

    const int smem = RP * PSH * 2;   // 83200 B
    (void)cudaFuncSetAttribute(lstm_fused_kernel,
                               cudaFuncAttributeMaxDynamicSharedMemorySize, smem);
    lstm_fused_kernel<<<GRID, NTHR, smem>>>(x, lengths, out);
}

// round 14
// speedup vs baseline: 2.2892x; 1.0405x over previous
#include <cuda_runtime.h>
#include <cuda_fp16.h>
#include <math.h>
#include <stdint.h>

#define NSEQ 10000
#define LSEQ 32
#define DIM  256
#define GDIM 1024
#define GRID 148
#define NTHR 256
#define RP   80          // padded rows per CTA (5 x m16 tiles)
#define PSH  776         // panel row stride in halves: 388 words, mod 32 = 4 -> A-loads conflict-free
#define CW   260         // c-state row stride in floats: mod 32 = 4 -> epilogue conflict-free

// panel columns: [0,256) = x_t ; [256,512) = h buffer 0 ; [512,768) = h buffer 1

// ---------------- device scratch (no runtime allocation allowed) ----------------
__device__ __half g_Whalf[524288];       // fused [W_ih;W_hh] in fp16 B-fragment order
__device__ float  g_bias[GDIM];          // b_ih + b_hh

// ---------------- helpers ----------------
__device__ __forceinline__ float sigf(float x) {
    return __fdividef(1.0f, 1.0f + __expf(-x));
}
__device__ __forceinline__ float tanhf_(float x) {
    return fmaf(2.0f, __fdividef(1.0f, 1.0f + __expf(-2.0f * x)), -1.0f);
}
__device__ __forceinline__ void mma_f16(float c[4],
                                        uint32_t a0, uint32_t a1, uint32_t a2, uint32_t a3,
                                        uint32_t b0, uint32_t b1) {
    asm volatile(
        "mma.sync.aligned.m16n8k16.row.col.f32.f16.f16.f32 "
        "{%0,%1,%2,%3},{%4,%5,%6,%7},{%8,%9},{%0,%1,%2,%3};"
        : "+f"(c[0]), "+f"(c[1]), "+f"(c[2]), "+f"(c[3])
        : "r"(a0), "r"(a1), "r"(a2), "r"(a3), "r"(b0), "r"(b1));
}

// ---------------- prep: fp16 B-fragment weights + folded bias (unchanged from R12) ----------------
__global__ void prep_kernel(const float* __restrict__ W_ih, const float* __restrict__ W_hh,
                            const float* __restrict__ b_ih, const float* __restrict__ b_hh) {
    int idx0 = blockIdx.x * blockDim.x + threadIdx.x;
    for (int idx = idx0; idx < 524288; idx += gridDim.x * blockDim.x) {
        int q    = idx & 3;            // 0,1 -> b0 halves; 2,3 -> b1 halves
        int lane = (idx >> 2) & 31;
        int ks   = (idx >> 7) & 31;
        int s8   = idx >> 12;
        int g    = lane >> 2, tig = lane & 3;
        int r    = q >> 1, hh = q & 1;
        int k    = ks * 16 + tig * 2 + r * 8 + hh;
        int p    = s8 * 8 + g;
        int nt = p >> 8, p8 = p & 255;
        int w = p8 >> 5, c32 = p8 & 31, s = c32 >> 3, c8 = c32 & 7;
        int u    = ((s >> 1) << 2) + (c8 >> 1);
        int gate = ((s & 1) << 1) + (c8 & 1);
        int j    = nt * 64 + w * 8 + u;
        int row  = gate * 256 + j;
        float v  = (k < 256) ? W_ih[row * 256 + k] : W_hh[row * 256 + (k - 256)];
        g_Whalf[idx] = __float2half(v);
    }
    if (idx0 < GDIM) g_bias[idx0] = b_ih[idx0] + b_hh[idx0];
}

// ---------------- fused persistent LSTM: all state resident in smem ----------------
__global__ __launch_bounds__(NTHR, 1)
void lstm_fused_kernel(const float* __restrict__ x, const int* __restrict__ lengths,
                       float* __restrict__ out) {
    extern __shared__ __half smem_raw[];
    __half* panel = smem_raw;                          // [RP][PSH] halves
    float*  cst   = (float*)(smem_raw + RP * PSH);     // [RP][CW] fp32
    __shared__ float sbias[GDIM];
    __shared__ int   slen[RP];

    const int bid = blockIdx.x;
    const int n0  = (bid * NSEQ) / GRID;
    const int n1  = ((bid + 1) * NSEQ) / GRID;
    const int R   = n1 - n0;           // 67 or 68
    const int tid = threadIdx.x;
    const int w   = tid >> 5, lane = tid & 31, g = lane >> 2, tig = lane & 3;

    for (int i = tid; i < GDIM; i += NTHR) sbias[i] = g_bias[i];
    for (int i = tid; i < RP; i += NTHR)   slen[i] = (i < R) ? lengths[n0 + i] : 0;
    for (int i = tid; i < RP * PSH / 2; i += NTHR) ((uint32_t*)panel)[i] = 0u;
    for (int i = tid; i < RP * CW; i += NTHR) cst[i] = 0.0f;
    __syncthreads();

    const uint2* gW2 = (const uint2*)&g_Whalf[0];

    for (int t = 0; t < LSEQ; t++) {
        // ---- stage x_t as fp16 (rows < R; pad rows stay zero) ----
        const float4* xg = (const float4*)(x + (size_t)n0 * LSEQ * DIM + (size_t)t * DIM);
        for (int i = tid; i < R * 64; i += NTHR) {
            int r = i >> 6, c = i & 63;
            float4 v = xg[(size_t)r * 2048 + c];   // row stride = LSEQ*DIM/4
            *(__half2*)&panel[r * PSH + c * 4]     = __floats2half2_rn(v.x, v.y);
            *(__half2*)&panel[r * PSH + c * 4 + 2] = __floats2half2_rn(v.z, v.w);
        }
        __syncthreads();

        const int hrd = 256 + (t & 1) * 256;           // h_t read columns
        const int hwr = 256 + ((t + 1) & 1) * 256;     // h_{t+1} write columns

        for (int nt = 0; nt < 4; nt++) {
            const int jcol = nt * 64 + w * 8 + tig;
            const float bi0 = sbias[jcol],       bf0 = sbias[256 + jcol];
            const float bg0 = sbias[512 + jcol], bo0 = sbias[768 + jcol];
            const float bi1 = sbias[jcol + 4],       bf1 = sbias[256 + jcol + 4];
            const float bg1 = sbias[512 + jcol + 4], bo1 = sbias[768 + jcol + 4];

            float C[5][4][4];
#pragma unroll
            for (int m = 0; m < 5; m++)
#pragma unroll
                for (int s = 0; s < 4; s++)
#pragma unroll
                    for (int q = 0; q < 4; q++) C[m][s][q] = 0.0f;

            const uint2* bp[4];
#pragma unroll
            for (int s = 0; s < 4; s++) {
                int s8 = nt * 32 + w * 4 + s;
                bp[s] = gW2 + (size_t)s8 * 1024 + lane;
            }

            int rowb[5];
#pragma unroll
            for (int m = 0; m < 5; m++) rowb[m] = (m * 16 + g) * PSH;

            // ---- half 1: ks in [0,16) -> A from x columns (base 0) ----
            {
                uint2 Bc[4];
#pragma unroll
                for (int s = 0; s < 4; s++) Bc[s] = bp[s][0];
#pragma unroll 2
                for (int ks = 0; ks < 16; ks++) {
                    uint2 Bn[4];
                    int ks2 = ks + 1;   // [1,16] valid (ks=16 row exists)
#pragma unroll
                    for (int s = 0; s < 4; s++) Bn[s] = bp[s][ks2 * 32];
                    const int k0 = ks * 16 + tig * 2;
#pragma unroll
                    for (int m = 0; m < 5; m++) {
                        const __half* ap = panel + rowb[m] + k0;
                        uint32_t a0 = *(const uint32_t*)ap;
                        uint32_t a2 = *(const uint32_t*)(ap + 8);
                        uint32_t a1 = *(const uint32_t*)(ap + 8 * PSH);
                        uint32_t a3 = *(const uint32_t*)(ap + 8 * PSH + 8);
#pragma unroll
                        for (int s = 0; s < 4; s++)
                            mma_f16(C[m][s], a0, a1, a2, a3, Bc[s].x, Bc[s].y);
                    }
#pragma unroll
                    for (int s = 0; s < 4; s++) Bc[s] = Bn[s];
                }
            }
            // ---- half 2: ks in [16,32) -> A from h columns (uniform base hrd-256) ----
            {
                uint2 Bc[4];
#pragma unroll
                for (int s = 0; s < 4; s++) Bc[s] = bp[s][16 * 32];
                const int hoff = hrd - 256;   // 0 or 256, loop-invariant uniform
#pragma unroll 2
                for (int ks = 16; ks < 32; ks++) {
                    uint2 Bn[4];
                    int ks2 = (ks < 31) ? ks + 1 : 31;
#pragma unroll
                    for (int s = 0; s < 4; s++) Bn[s] = bp[s][ks2 * 32];
                    const int k0 = ks * 16 + tig * 2 + hoff;
#pragma unroll
                    for (int m = 0; m < 5; m++) {
                        const __half* ap = panel + rowb[m] + k0;
                        uint32_t a0 = *(const uint32_t*)ap;
                        uint32_t a2 = *(const uint32_t*)(ap + 8);
                        uint32_t a1 = *(const uint32_t*)(ap + 8 * PSH);
                        uint32_t a3 = *(const uint32_t*)(ap + 8 * PSH + 8);
#pragma unroll
                        for (int s = 0; s < 4; s++)
                            mma_f16(C[m][s], a0, a1, a2, a3, Bc[s].x, Bc[s].y);
                    }
#pragma unroll
                    for (int s = 0; s < 4; s++) Bc[s] = Bn[s];
                }
            }

            // ---- epilogue: gates in registers, c in smem fp32, h written to next panel buffer ----
#pragma unroll
            for (int m = 0; m < 5; m++) {
                int r0 = m * 16 + g, r1 = r0 + 8;
                bool v0 = t < slen[r0], v1 = t < slen[r1];
                int cr0 = r0 * CW + jcol, cr1 = r1 * CW + jcol;
                int pr0 = r0 * PSH, pr1 = r1 * PSH;
                {   // q0: unit jcol, row r0
                    float cold = cst[cr0];
                    float ii = sigf(C[m][0][0] + bi0), ff = sigf(C[m][0][1] + bf0);
                    float gg = tanhf_(C[m][1][0] + bg0), oo = sigf(C[m][1][1] + bo0);
                    float c2 = fmaf(ff, cold, ii * gg);
                    float h2 = oo * tanhf_(c2);
                    cst[cr0] = v0 ? c2 : cold;
                    panel[pr0 + hwr + jcol] =
                        v0 ? __float2half(h2) : panel[pr0 + hrd + jcol];
                }
                {   // q1: unit jcol, row r1
                    float cold = cst[cr1];
                    float ii = sigf(C[m][0][2] + bi0), ff = sigf(C[m][0][3] + bf0);
                    float gg = tanhf_(C[m][1][2] + bg0), oo = sigf(C[m][1][3] + bo0);
                    float c2 = fmaf(ff, cold, ii * gg);
                    float h2 = oo * tanhf_(c2);
                    cst[cr1] = v1 ? c2 : cold;
                    panel[pr1 + hwr + jcol] =
                        v1 ? __float2half(h2) : panel[pr1 + hrd + jcol];
                }
                {   // q2: unit jcol+4, row r0
                    float cold = cst[cr0 + 4];
                    float ii = sigf(C[m][2][0] + bi1), ff = sigf(C[m][2][1] + bf1);
                    float gg = tanhf_(C[m][3][0] + bg1), oo = sigf(C[m][3][1] + bo1);
                    float c2 = fmaf(ff, cold, ii * gg);
                    float h2 = oo * tanhf_(c2);
                    cst[cr0 + 4] = v0 ? c2 : cold;
                    panel[pr0 + hwr + jcol + 4] =
                        v0 ? __float2half(h2) : panel[pr0 + hrd + jcol + 4];
                }
                {   // q3: unit jcol+4, row r1
                    float cold = cst[cr1 + 4];
                    float ii = sigf(C[m][2][2] + bi1), ff = sigf(C[m][2][3] + bf1);
                    float gg = tanhf_(C[m][3][2] + bg1), oo = sigf(C[m][3][3] + bo1);
                    float c2 = fmaf(ff, cold, ii * gg);
                    float h2 = oo * tanhf_(c2);
                    cst[cr1 + 4] = v1 ? c2 : cold;
                    panel[pr1 + hwr + jcol + 4] =
                        v1 ? __float2half(h2) : panel[pr1 + hrd + jcol + 4];
                }
            }
        }
        __syncthreads();   // h_{t+1}/c fully written; x region free for restaging
    }

    // ---- write final h: h_32 lives in buffer (LSEQ&1)=0 -> cols [256,512) ----
    for (int i = tid; i < R * 256; i += NTHR) {
        int r = i >> 8, j = i & 255;
        out[(size_t)(n0 + r) * DIM + j] = __half2float(panel[r * PSH + 256 + j]);
    }
}

// ---------------- launch ----------------
extern "C" void kernel_launch(void* const* d_in, const int* in_sizes, int n_in,
                              void* d_out, int out_size) {
    const float* x       = (const float*)d_in[0];
    const int*   lengths = (const int*)d_in[1];
    const float* W_ih    = (const float*)d_in[2];
    const float* W_hh    = (const float*)d_in[3];
    const float* b_ih    = (const float*)d_in[4];
    const float* b_hh    = (const float*)d_in[5];
    float*       out     = (float*)d_out;
    (void)in_sizes; (void)n_in; (void)out_size;

    prep_kernel<<<512, 256>>>(W_ih, W_hh, b_ih, b_hh);

    const int smem = RP * PSH * 2 + RP * CW * 4;   // 124160 + 83200 = 207360 B
    (void)cudaFuncSetAttribute(lstm_fused_kernel,
                               cudaFuncAttributeMaxDynamicSharedMemorySize, smem);
    lstm_fused_kernel<<<GRID, NTHR, smem>>>(x, lengths, out);
}

// round 17
// speedup vs baseline: 2.5375x; 1.1084x over previous
#include <cuda_runtime.h>
#include <cuda_fp16.h>
#include <math.h>
#include <stdint.h>

#define NSEQ 10000
#define LSEQ 32
#define DIM  256
#define GDIM 1024
#define GRID 148
#define NTHR 256
#define RP   80          // padded rows per CTA (5 x m16 tiles)
#define PSH  776         // panel row stride in halves: 388 words, mod 32 = 4 -> conflict-free
#define CW   260         // c-state row stride in floats: mod 32 = 4 -> epilogue conflict-free

// panel columns: [0,256) = x_t ; [256,512) = h buffer 0 ; [512,768) = h buffer 1

// ---------------- device scratch (no runtime allocation allowed) ----------------
__device__ __half g_Whalf[524288];       // fused [W_ih;W_hh] in fp16 B-fragment order
__device__ float  g_bias[GDIM];          // b_ih + b_hh

// ---------------- helpers ----------------
__device__ __forceinline__ float tanh_ap(float x) {
    float y; asm("tanh.approx.f32 %0, %1;" : "=f"(y) : "f"(x)); return y;
}
__device__ __forceinline__ float sigf(float x) {
    return fmaf(0.5f, tanh_ap(0.5f * x), 0.5f);
}
__device__ __forceinline__ float tanhf_(float x) {
    return tanh_ap(x);
}
__device__ __forceinline__ void mma_f16(float c[4],
                                        uint32_t a0, uint32_t a1, uint32_t a2, uint32_t a3,
                                        uint32_t b0, uint32_t b1) {
    asm volatile(
        "mma.sync.aligned.m16n8k16.row.col.f32.f16.f16.f32 "
        "{%0,%1,%2,%3},{%4,%5,%6,%7},{%8,%9},{%0,%1,%2,%3};"
        : "+f"(c[0]), "+f"(c[1]), "+f"(c[2]), "+f"(c[3])
        : "r"(a0), "r"(a1), "r"(a2), "r"(a3), "r"(b0), "r"(b1));
}
__device__ __forceinline__ void ldsm4(uint32_t& a0, uint32_t& a1, uint32_t& a2, uint32_t& a3,
                                      uint32_t addr) {
    asm volatile("ldmatrix.sync.aligned.m8n8.x4.shared.b16 {%0,%1,%2,%3}, [%4];"
                 : "=r"(a0), "=r"(a1), "=r"(a2), "=r"(a3) : "r"(addr));
}

// ---------------- prep: fp16 B-fragment weights + folded bias (unchanged) ----------------
__global__ void prep_kernel(const float* __restrict__ W_ih, const float* __restrict__ W_hh,
                            const float* __restrict__ b_ih, const float* __restrict__ b_hh) {
    int idx0 = blockIdx.x * blockDim.x + threadIdx.x;
    for (int idx = idx0; idx < 524288; idx += gridDim.x * blockDim.x) {
        int q    = idx & 3;            // 0,1 -> b0 halves; 2,3 -> b1 halves
        int lane = (idx >> 2) & 31;
        int ks   = (idx >> 7) & 31;
        int s8   = idx >> 12;
        int g    = lane >> 2, tig = lane & 3;
        int r    = q >> 1, hh = q & 1;
        int k    = ks * 16 + tig * 2 + r * 8 + hh;
        int p    = s8 * 8 + g;
        int nt = p >> 8, p8 = p & 255;
        int w = p8 >> 5, c32 = p8 & 31, s = c32 >> 3, c8 = c32 & 7;
        int u    = ((s >> 1) << 2) + (c8 >> 1);
        int gate = ((s & 1) << 1) + (c8 & 1);
        int j    = nt * 64 + w * 8 + u;
        int row  = gate * 256 + j;
        float v  = (k < 256) ? W_ih[row * 256 + k] : W_hh[row * 256 + (k - 256)];
        g_Whalf[idx] = __float2half(v);
    }
    if (idx0 < GDIM) g_bias[idx0] = b_ih[idx0] + b_hh[idx0];
}

// ---------------- fused persistent LSTM: all state resident in smem ----------------
__global__ __launch_bounds__(NTHR, 1)
void lstm_fused_kernel(const float* __restrict__ x, const int* __restrict__ lengths,
                       float* __restrict__ out) {
    extern __shared__ __half smem_raw[];
    __half* panel = smem_raw;                          // [RP][PSH] halves
    float*  cst   = (float*)(smem_raw + RP * PSH);     // [RP][CW] fp32
    __shared__ float sbias[GDIM];
    __shared__ int   slen[RP];

    const int bid = blockIdx.x;
    const int n0  = (bid * NSEQ) / GRID;
    const int n1  = ((bid + 1) * NSEQ) / GRID;
    const int R   = n1 - n0;           // 67 or 68
    const int tid = threadIdx.x;
    const int w   = tid >> 5, lane = tid & 31, g = lane >> 2, tig = lane & 3;

    for (int i = tid; i < GDIM; i += NTHR) sbias[i] = g_bias[i];
    for (int i = tid; i < RP; i += NTHR)   slen[i] = (i < R) ? lengths[n0 + i] : 0;
    for (int i = tid; i < RP * PSH / 2; i += NTHR) ((uint32_t*)panel)[i] = 0u;
    for (int i = tid; i < RP * CW; i += NTHR) cst[i] = 0.0f;
    __syncthreads();

    const uint2* gW2 = (const uint2*)&g_Whalf[0];
    // ldmatrix per-lane base (halves): row = m*16 + (lane&15), k += (lane>>4)*8
    const uint32_t pbase = (uint32_t)__cvta_generic_to_shared(panel);
    const uint32_t lrow  = (uint32_t)(lane & 15) * PSH + (uint32_t)((lane >> 4) << 3);

    for (int t = 0; t < LSEQ; t++) {
        // ---- stage x_t as fp16 (rows < R; pad rows stay zero) ----
        const float4* xg = (const float4*)(x + (size_t)n0 * LSEQ * DIM + (size_t)t * DIM);
        for (int i = tid; i < R * 64; i += NTHR) {
            int r = i >> 6, c = i & 63;
            float4 v = xg[(size_t)r * 2048 + c];   // row stride = LSEQ*DIM/4
            *(__half2*)&panel[r * PSH + c * 4]     = __floats2half2_rn(v.x, v.y);
            *(__half2*)&panel[r * PSH + c * 4 + 2] = __floats2half2_rn(v.z, v.w);
        }
        __syncthreads();

        const int hrd = 256 + (t & 1) * 256;           // h_t read columns
        const int hwr = 256 + ((t + 1) & 1) * 256;     // h_{t+1} write columns

        for (int nt = 0; nt < 4; nt++) {
            const int jcol = nt * 64 + w * 8 + tig;
            const float bi0 = sbias[jcol],       bf0 = sbias[256 + jcol];
            const float bg0 = sbias[512 + jcol], bo0 = sbias[768 + jcol];
            const float bi1 = sbias[jcol + 4],       bf1 = sbias[256 + jcol + 4];
            const float bg1 = sbias[512 + jcol + 4], bo1 = sbias[768 + jcol + 4];

            float C[5][4][4];
#pragma unroll
            for (int m = 0; m < 5; m++)
#pragma unroll
                for (int s = 0; s < 4; s++)
#pragma unroll
                    for (int q = 0; q < 4; q++) C[m][s][q] = 0.0f;

            const uint2* bp[4];
#pragma unroll
            for (int s = 0; s < 4; s++) {
                int s8 = nt * 32 + w * 4 + s;
                bp[s] = gW2 + (size_t)s8 * 1024 + lane;
            }

            uint32_t ldb[5];   // ldmatrix byte base per m-tile
#pragma unroll
            for (int m = 0; m < 5; m++)
                ldb[m] = pbase + 2u * ((uint32_t)(m * 16) * PSH + lrow);

            // ---- half 1: ks in [0,16) -> A from x columns (base 0) ----
            {
                uint2 Bc[4];
#pragma unroll
                for (int s = 0; s < 4; s++) Bc[s] = bp[s][0];
#pragma unroll 2
                for (int ks = 0; ks < 16; ks++) {
                    uint2 Bn[4];
                    int ks2 = ks + 1;   // [1,16] valid (ks=16 row exists)
#pragma unroll
                    for (int s = 0; s < 4; s++) Bn[s] = bp[s][ks2 * 32];
                    const uint32_t koff = 2u * (uint32_t)(ks * 16);
#pragma unroll
                    for (int m = 0; m < 5; m++) {
                        uint32_t a0, a1, a2, a3;
                        ldsm4(a0, a1, a2, a3, ldb[m] + koff);
#pragma unroll
                        for (int s = 0; s < 4; s++)
                            mma_f16(C[m][s], a0, a1, a2, a3, Bc[s].x, Bc[s].y);
                    }
#pragma unroll
                    for (int s = 0; s < 4; s++) Bc[s] = Bn[s];
                }
            }
            // ---- half 2: ks in [16,32) -> A from h columns (uniform base hrd-256) ----
            {
                uint2 Bc[4];
#pragma unroll
                for (int s = 0; s < 4; s++) Bc[s] = bp[s][16 * 32];
                const uint32_t hoff2 = 2u * (uint32_t)(hrd - 256);  // 0 or 512 bytes
#pragma unroll 2
                for (int ks = 16; ks < 32; ks++) {
                    uint2 Bn[4];
                    int ks2 = (ks < 31) ? ks + 1 : 31;
#pragma unroll
                    for (int s = 0; s < 4; s++) Bn[s] = bp[s][ks2 * 32];
                    const uint32_t koff = 2u * (uint32_t)(ks * 16) + hoff2;
#pragma unroll
                    for (int m = 0; m < 5; m++) {
                        uint32_t a0, a1, a2, a3;
                        ldsm4(a0, a1, a2, a3, ldb[m] + koff);
#pragma unroll
                        for (int s = 0; s < 4; s++)
                            mma_f16(C[m][s], a0, a1, a2, a3, Bc[s].x, Bc[s].y);
                    }
#pragma unroll
                    for (int s = 0; s < 4; s++) Bc[s] = Bn[s];
                }
            }

            // ---- epilogue: gates in registers, c in smem fp32, h to next panel buffer ----
#pragma unroll
            for (int m = 0; m < 5; m++) {
                int r0 = m * 16 + g, r1 = r0 + 8;
                bool v0 = t < slen[r0], v1 = t < slen[r1];
                int cr0 = r0 * CW + jcol, cr1 = r1 * CW + jcol;
                int pr0 = r0 * PSH, pr1 = r1 * PSH;
                {   // q0: unit jcol, row r0
                    float cold = cst[cr0];
                    float ii = sigf(C[m][0][0] + bi0), ff = sigf(C[m][0][1] + bf0);
                    float gg = tanhf_(C[m][1][0] + bg0), oo = sigf(C[m][1][1] + bo0);
                    float c2 = fmaf(ff, cold, ii * gg);
                    float h2 = oo * tanhf_(c2);
                    cst[cr0] = v0 ? c2 : cold;
                    panel[pr0 + hwr + jcol] =
                        v0 ? __float2half(h2) : panel[pr0 + hrd + jcol];
                }
                {   // q1: unit jcol, row r1
                    float cold = cst[cr1];
                    float ii = sigf(C[m][0][2] + bi0), ff = sigf(C[m][0][3] + bf0);
                    float gg = tanhf_(C[m][1][2] + bg0), oo = sigf(C[m][1][3] + bo0);
                    float c2 = fmaf(ff, cold, ii * gg);
                    float h2 = oo * tanhf_(c2);
                    cst[cr1] = v1 ? c2 : cold;
                    panel[pr1 + hwr + jcol] =
                        v1 ? __float2half(h2) : panel[pr1 + hrd + jcol];
                }
                {   // q2: unit jcol+4, row r0
                    float cold = cst[cr0 + 4];
                    float ii = sigf(C[m][2][0] + bi1), ff = sigf(C[m][2][1] + bf1);
                    float gg = tanhf_(C[m][3][0] + bg1), oo = sigf(C[m][3][1] + bo1);
                    float c2 = fmaf(ff, cold, ii * gg);
                    float h2 = oo * tanhf_(c2);
                    cst[cr0 + 4] = v0 ? c2 : cold;
                    panel[pr0 + hwr + jcol + 4] =
                        v0 ? __float2half(h2) : panel[pr0 + hrd + jcol + 4];
                }
                {   // q3: unit jcol+4, row r1
                    float cold = cst[cr1 + 4];
                    float ii = sigf(C[m][2][2] + bi1), ff = sigf(C[m][2][3] + bf1);
                    float gg = tanhf_(C[m][3][2] + bg1), oo = sigf(C[m][3][3] + bo1);
                    float c2 = fmaf(ff, cold, ii * gg);
                    float h2 = oo * tanhf_(c2);
                    cst[cr1 + 4] = v1 ? c2 : cold;
                    panel[pr1 + hwr + jcol + 4] =
                        v1 ? __float2half(h2) : panel[pr1 + hrd + jcol + 4];
                }
            }
        }
        __syncthreads();   // h_{t+1}/c fully written; x region free for restaging
    }

    // ---- write final h: h_32 lives in buffer (LSEQ&1)=0 -> cols [256,512) ----
    for (int i = tid; i < R * 256; i += NTHR) {
        int r = i >> 8, j = i & 255;
        out[(size_t)(n0 + r) * DIM + j] = __half2float(panel[r * PSH + 256 + j]);
    }
}

// ---------------- launch ----------------
extern "C" void kernel_launch(void* const* d_in, const int* in_sizes, int n_in,
                              void* d_out, int out_size) {
    const float* x       = (const float*)d_in[0];
    const int*   lengths = (const int*)d_in[1];
    const float* W_ih    = (const float*)d_in[2];
    const float* W_hh    = (const float*)d_in[3];
    const float* b_ih    = (const float*)d_in[4];
    const float* b_hh    = (const float*)d_in[5];
    float*       out     = (float*)d_out;
    (void)in_sizes; (void)n_in; (void)out_size;

    prep_kernel<<<512, 256>>>(W_ih, W_hh, b_ih, b_hh);

    const int smem = RP * PSH * 2 + RP * CW * 4;   // 124160 + 83200 = 207360 B
    (void)cudaFuncSetAttribute(lstm_fused_kernel,
                               cudaFuncAttributeMaxDynamicSharedMemorySize, smem);
    lstm_fused_kernel<<<GRID, NTHR, smem>>>(x, lengths, out);
}